// round 15
// baseline (speedup 1.0000x reference)
#include <cuda_runtime.h>
#include <cuda_bf16.h>
#include <math.h>

#define D 128
#define GMAX 4096
#define NMAX 500000

__device__ float g_h[GMAX * D];
__device__ float g_c[GMAX * D];
__device__ float g_r[GMAX * D];
__device__ float g_gates[GMAX * 4 * D];   // PERMUTED layout: col n' = d*4 + gate
__device__ float g_bias[4 * D];           // original order (for init_state)
__device__ float g_bias2[4 * D];          // permuted order  (for epilogue)
__device__ int   g_segstart[GMAX + 1];

// bf16 split operands for tensor-core GEMM (16B-aligned for cp.async):
__device__ __align__(16) __nv_bfloat16 g_A[GMAX * 512];
// B panel [512 n'][512 k]: rows permuted n' = d*4+gate; k<256 hi, k>=256 lo
__device__ __align__(16) __nv_bfloat16 g_Wb[512 * 512];

__device__ __forceinline__ float sigf(float v) {
    return 1.0f / (1.0f + __expf(-v));
}

__device__ __forceinline__ unsigned smem_u32(const void* p) {
    return (unsigned)__cvta_generic_to_shared(p);
}
__device__ __forceinline__ void cp16(void* dst, const void* src) {
    asm volatile("cp.async.cg.shared.global [%0], [%1], 16;\n"
                 :: "r"(smem_u32(dst)), "l"(src));
}
__device__ __forceinline__ void cp_commit() {
    asm volatile("cp.async.commit_group;\n");
}
template <int N> __device__ __forceinline__ void cp_wait() {
    asm volatile("cp.async.wait_group %0;\n" :: "n"(N));
}
__device__ __forceinline__ void ldsm4(unsigned& r0, unsigned& r1, unsigned& r2,
                                      unsigned& r3, const void* p) {
    asm volatile("ldmatrix.sync.aligned.m8n8.x4.shared.b16 {%0,%1,%2,%3}, [%4];"
                 : "=r"(r0), "=r"(r1), "=r"(r2), "=r"(r3)
                 : "r"(smem_u32(p)));
}
__device__ __forceinline__ void pfL2(const void* p) {
    asm volatile("prefetch.global.L2 [%0];" :: "l"(p));
}

// ---------------------------------------------------------------------------
// prep: permuted split weights, both bias orders, segment boundaries
// ---------------------------------------------------------------------------
__global__ void prep_kernel(const float* __restrict__ W_ih,
                            const float* __restrict__ W_hh,
                            const float* __restrict__ b_ih,
                            const float* __restrict__ b_hh,
                            const void* __restrict__ index_raw,
                            int N, int G) {
    int tid = blockIdx.x * blockDim.x + threadIdx.x;

    if (tid < 512 * 512) {
        int np = tid >> 9, k = tid & 511;
        int orig_n = (np & 3) * 128 + (np >> 2);   // n' = d*4 + gate
        int kk = k & 255;
        float w = W_ih[(size_t)orig_n * 256 + kk];
        if (kk < D) w += W_hh[(size_t)orig_n * D + kk];
        __nv_bfloat16 hi = __float2bfloat16(w);
        if (k < 256) g_Wb[tid] = hi;
        else         g_Wb[tid] = __float2bfloat16(w - __bfloat162float(hi));
    }
    if (tid < 4 * D) {
        g_bias[tid] = b_ih[tid] + b_hh[tid];
        int orig = (tid & 3) * 128 + (tid >> 2);
        g_bias2[tid] = b_ih[orig] + b_hh[orig];
    }

    if (tid <= G) {
        const int* p32 = (const int*)index_raw;
        int j1 = N - 1;
        if ((j1 & 1) == 0) j1--;
        int is64 = 1;
        if (j1 >= 5) {
            if (p32[j1] != 0 || p32[j1 - 2] != 0 || p32[j1 - 4] != 0) is64 = 0;
        }
        const long long* p64 = (const long long*)index_raw;
        int lo = 0, hi = N;
        while (lo < hi) {
            int mid = (lo + hi) >> 1;
            long long v = is64 ? p64[mid] : (long long)p32[mid];
            if (v < (long long)tid) lo = mid + 1; else hi = mid;
        }
        g_segstart[tid] = lo;
    }
}

// ---------------------------------------------------------------------------
__global__ void init_state_kernel(int G) {
    int tid = blockIdx.x * blockDim.x + threadIdx.x;
    if (tid >= G * D) return;
    int row = tid / D, d = tid % D;
    float bi = g_bias[d], bg = g_bias[2 * D + d], bo = g_bias[3 * D + d];
    float c = sigf(bi) * tanhf(bg);
    float h = sigf(bo) * tanhf(c);
    g_c[tid] = c;
    g_h[tid] = h;
    __nv_bfloat16 hh = __float2bfloat16(h);
    g_A[(size_t)row * 512 + d] = hh;
    g_A[(size_t)row * 512 + 256 + d] = __float2bfloat16(h - __bfloat162float(hh));
}

// ---------------------------------------------------------------------------
// segment attention (direct LDG) + depth-1 L2 prefetch (R13 proven config).
// ---------------------------------------------------------------------------
__global__ void __launch_bounds__(256) segment_kernel(const float* __restrict__ x,
                                                      float* __restrict__ out,
                                                      int writeA, int rev) {
    int g = rev ? ((int)gridDim.x - 1 - (int)blockIdx.x) : (int)blockIdx.x;
    int start = g_segstart[g];
    int end   = g_segstart[g + 1];

    __shared__ __align__(16) float wacc[32][D];
    __shared__ __align__(16) float qs[D];
    __shared__ float ws[32];
    __shared__ float winv;

    int tid = threadIdx.x, warp = tid >> 5, lane = tid & 31;
    int grp = lane >> 3, sub = lane & 7;
    int gidx = warp * 4 + grp;
    unsigned gmask = 0xFFu << (grp * 8);

    if (tid < D) qs[tid] = g_h[(size_t)g * D + tid];
    __syncthreads();

    const float4* q4 = (const float4*)qs;
    float4 q0 = q4[sub], q1 = q4[sub + 8], q2 = q4[sub + 16], q3 = q4[sub + 24];

    float s = 0.0f;
    float4 a0 = make_float4(0.f, 0.f, 0.f, 0.f);
    float4 a1 = a0, a2 = a0, a3 = a0;

    if (start < end) {
        const float4* fp = (const float4*)(x + (size_t)start * D);
        float4 f0 = fp[sub], f1 = fp[sub + 8], f2 = fp[sub + 16], f3 = fp[sub + 24];
        float m = f0.x * q0.x + f0.y * q0.y + f0.z * q0.z + f0.w * q0.w
                + f1.x * q1.x + f1.y * q1.y + f1.z * q1.z + f1.w * q1.w
                + f2.x * q2.x + f2.y * q2.y + f2.z * q2.z + f2.w * q2.w
                + f3.x * q3.x + f3.y * q3.y + f3.z * q3.z + f3.w * q3.w;
        m += __shfl_xor_sync(gmask, m, 1);
        m += __shfl_xor_sync(gmask, m, 2);
        m += __shfl_xor_sync(gmask, m, 4);

        for (int row = start + gidx; row < end; row += 32) {
            const float4* xp = (const float4*)(x + (size_t)row * D);
            int nrow = row + 32;
            if (nrow < end) {
                const char* np = (const char*)(x + (size_t)nrow * D) + sub * 16;
                pfL2(np); pfL2(np + 128); pfL2(np + 256); pfL2(np + 384);
            }
            float4 v0 = xp[sub], v1 = xp[sub + 8];
            float4 v2 = xp[sub + 16], v3 = xp[sub + 24];
            float d = v0.x * q0.x + v0.y * q0.y + v0.z * q0.z + v0.w * q0.w
                    + v1.x * q1.x + v1.y * q1.y + v1.z * q1.z + v1.w * q1.w
                    + v2.x * q2.x + v2.y * q2.y + v2.z * q2.z + v2.w * q2.w
                    + v3.x * q3.x + v3.y * q3.y + v3.z * q3.z + v3.w * q3.w;
            d += __shfl_xor_sync(gmask, d, 1);
            d += __shfl_xor_sync(gmask, d, 2);
            d += __shfl_xor_sync(gmask, d, 4);
            float p = __expf(d - m);
            s += p;
            a0.x += p * v0.x; a0.y += p * v0.y; a0.z += p * v0.z; a0.w += p * v0.w;
            a1.x += p * v1.x; a1.y += p * v1.y; a1.z += p * v1.z; a1.w += p * v1.w;
            a2.x += p * v2.x; a2.y += p * v2.y; a2.z += p * v2.z; a2.w += p * v2.w;
            a3.x += p * v3.x; a3.y += p * v3.y; a3.z += p * v3.z; a3.w += p * v3.w;
        }
    }

    float4* wp = (float4*)wacc[gidx];
    wp[sub] = a0; wp[sub + 8] = a1; wp[sub + 16] = a2; wp[sub + 24] = a3;
    if (sub == 0) ws[gidx] = s;
    __syncthreads();

    if (tid == 0) {
        float S = 0.0f;
        #pragma unroll
        for (int i = 0; i < 32; i++) S += ws[i];
        winv = 1.0f / fmaxf(S, 1e-16f);
    }
    __syncthreads();

    if (tid < D) {
        float inv = winv;
        float r = 0.0f;
        #pragma unroll
        for (int w = 0; w < 32; w++) r += wacc[w][tid];
        r *= inv;
        g_r[(size_t)g * D + tid] = r;
        if (writeA) {
            __nv_bfloat16 hh = __float2bfloat16(r);
            g_A[(size_t)g * 512 + 128 + tid] = hh;
            g_A[(size_t)g * 512 + 384 + tid] = __float2bfloat16(r - __bfloat162float(hh));
        }
        if (out) {
            out[(size_t)g * 256 + tid] = qs[tid];
            out[(size_t)g * 256 + 128 + tid] = r;
        }
    }
}

// ---------------------------------------------------------------------------
// half-GEMM with d-interleaved gate columns (n' = d*4 + gate).
// part=0 (accum=0): write raw permuted gates.
// part=1 (accum=1): accumulate + bias + FUSED LSTM epilogue:
//   lane-pair shfl gathers {i,f} + {g,o} of one (row,d); even lane updates
//   c, h and the A-panel hi/lo columns directly. No lstm_update kernel.
// ---------------------------------------------------------------------------
#define TS 8192
#define SSTG (4 * TS)

__device__ __forceinline__ __nv_bfloat16* swaddr(__nv_bfloat16* base, int row, int k) {
    int kb = k >> 3, ko = k & 7;
    return base + row * 64 + ((kb ^ (row & 7)) << 3) + ko;
}

__global__ void __launch_bounds__(256, 1) gemm_half(int part, int accum) {
    extern __shared__ __align__(16) __nv_bfloat16 sm[];

    int bm = blockIdx.x * 128;
    int bn = blockIdx.y * 128;
    int t = threadIdx.x, warp = t >> 5, lane = t & 31;
    int wm_ = (warp & 3) * 32;
    int wn_ = (warp >> 2) * 64;
    int gid = lane >> 2, tig = lane & 3;

    int a_row_off = (lane & 7) + (lane & 8);
    int a_k_off   = (lane >> 4) << 3;
    int b_row_off = (lane & 7) + ((lane >> 4) << 3);
    int b_k_off   = ((lane >> 3) & 1) << 3;

    float acc[2][8][4];
    #pragma unroll
    for (int mi = 0; mi < 2; mi++)
        #pragma unroll
        for (int ni = 0; ni < 8; ni++)
            #pragma unroll
            for (int cc = 0; cc < 4; cc++) acc[mi][ni][cc] = 0.0f;

    auto issue_load = [&](int stage, int c) {
        int kb = part * 128 + c * 64;
        __nv_bfloat16* st = sm + stage * SSTG;
        #pragma unroll
        for (int i = 0; i < 4; i++) {
            int idx = t + i * 256;
            int row = idx >> 3, c8 = idx & 7;
            unsigned sw = row * 64 + ((c8 ^ (row & 7)) << 3);
            const __nv_bfloat16* arow = g_A + (size_t)(bm + row) * 512;
            cp16(st + sw,            arow + kb + c8 * 8);
            cp16(st + TS + sw,       arow + 256 + kb + c8 * 8);
            const __nv_bfloat16* brow = g_Wb + (size_t)(bn + row) * 512;
            cp16(st + 2 * TS + sw,   brow + kb + c8 * 8);
            cp16(st + 3 * TS + sw,   brow + 256 + kb + c8 * 8);
        }
        cp_commit();
    };

    issue_load(0, 0);

    for (int c = 0; c < 2; c++) {
        if (c == 0) {
            issue_load(1, 1);
            cp_wait<1>();
        } else {
            cp_wait<0>();
        }
        __syncthreads();

        __nv_bfloat16* Ahi = sm + c * SSTG;
        __nv_bfloat16* Alo = Ahi + TS;
        __nv_bfloat16* Bhi = Ahi + 2 * TS;
        __nv_bfloat16* Blo = Ahi + 3 * TS;

        #pragma unroll
        for (int k0 = 0; k0 < 64; k0 += 16) {
            unsigned ah[2][4], al[2][4];
            #pragma unroll
            for (int mi = 0; mi < 2; mi++) {
                ldsm4(ah[mi][0], ah[mi][1], ah[mi][2], ah[mi][3],
                      swaddr(Ahi, wm_ + mi * 16 + a_row_off, k0 + a_k_off));
                ldsm4(al[mi][0], al[mi][1], al[mi][2], al[mi][3],
                      swaddr(Alo, wm_ + mi * 16 + a_row_off, k0 + a_k_off));
            }
            unsigned bh[4][4], bl[4][4];
            #pragma unroll
            for (int np = 0; np < 4; np++) {
                ldsm4(bh[np][0], bh[np][1], bh[np][2], bh[np][3],
                      swaddr(Bhi, wn_ + np * 16 + b_row_off, k0 + b_k_off));
                ldsm4(bl[np][0], bl[np][1], bl[np][2], bl[np][3],
                      swaddr(Blo, wn_ + np * 16 + b_row_off, k0 + b_k_off));
            }
            #pragma unroll
            for (int mi = 0; mi < 2; mi++) {
                #pragma unroll
                for (int ni = 0; ni < 8; ni++) {
                    int np = ni >> 1, hf = ni & 1;
                    asm volatile(
                        "mma.sync.aligned.m16n8k16.row.col.f32.bf16.bf16.f32 "
                        "{%0,%1,%2,%3}, {%4,%5,%6,%7}, {%8,%9}, {%0,%1,%2,%3};\n"
                        : "+f"(acc[mi][ni][0]), "+f"(acc[mi][ni][1]),
                          "+f"(acc[mi][ni][2]), "+f"(acc[mi][ni][3])
                        : "r"(ah[mi][0]), "r"(ah[mi][1]), "r"(ah[mi][2]), "r"(ah[mi][3]),
                          "r"(bh[np][hf * 2]), "r"(bh[np][hf * 2 + 1]));
                    asm volatile(
                        "mma.sync.aligned.m16n8k16.row.col.f32.bf16.bf16.f32 "
                        "{%0,%1,%2,%3}, {%4,%5,%6,%7}, {%8,%9}, {%0,%1,%2,%3};\n"
                        : "+f"(acc[mi][ni][0]), "+f"(acc[mi][ni][1]),
                          "+f"(acc[mi][ni][2]), "+f"(acc[mi][ni][3])
                        : "r"(ah[mi][0]), "r"(ah[mi][1]), "r"(ah[mi][2]), "r"(ah[mi][3]),
                          "r"(bl[np][hf * 2]), "r"(bl[np][hf * 2 + 1]));
                    asm volatile(
                        "mma.sync.aligned.m16n8k16.row.col.f32.bf16.bf16.f32 "
                        "{%0,%1,%2,%3}, {%4,%5,%6,%7}, {%8,%9}, {%0,%1,%2,%3};\n"
                        : "+f"(acc[mi][ni][0]), "+f"(acc[mi][ni][1]),
                          "+f"(acc[mi][ni][2]), "+f"(acc[mi][ni][3])
                        : "r"(al[mi][0]), "r"(al[mi][1]), "r"(al[mi][2]), "r"(al[mi][3]),
                          "r"(bh[np][hf * 2]), "r"(bh[np][hf * 2 + 1]));
                }
            }
        }
        __syncthreads();
    }

    if (!accum) {
        // part 0: write raw permuted gates
        #pragma unroll
        for (int mi = 0; mi < 2; mi++) {
            #pragma unroll
            for (int rr = 0; rr < 2; rr++) {
                int row = bm + wm_ + mi * 16 + rr * 8 + gid;
                #pragma unroll
                for (int ni = 0; ni < 8; ni++) {
                    int col = bn + wn_ + ni * 8 + tig * 2;
                    *(float2*)(g_gates + (size_t)row * 512 + col) =
                        make_float2(acc[mi][ni][rr * 2], acc[mi][ni][rr * 2 + 1]);
                }
            }
        }
    } else {
        // part 1: accumulate + bias + fused LSTM
        #pragma unroll
        for (int mi = 0; mi < 2; mi++) {
            #pragma unroll
            for (int rr = 0; rr < 2; rr++) {
                int row = bm + wm_ + mi * 16 + rr * 8 + gid;
                #pragma unroll
                for (int ni = 0; ni < 8; ni++) {
                    int col = bn + wn_ + ni * 8 + tig * 2;
                    float2 v = make_float2(acc[mi][ni][rr * 2], acc[mi][ni][rr * 2 + 1]);
                    float2 o = *(const float2*)(g_gates + (size_t)row * 512 + col);
                    v.x += o.x + g_bias2[col];
                    v.y += o.y + g_bias2[col + 1];
                    // tig even lanes hold {i,f}; tig odd lanes hold {g,o} (same row,d)
                    float ox = __shfl_xor_sync(0xffffffffu, v.x, 1);
                    float oy = __shfl_xor_sync(0xffffffffu, v.y, 1);
                    if ((tig & 1) == 0) {
                        int d = col >> 2;
                        float gi = v.x, gf = v.y, gg = ox, go = oy;
                        size_t hidx = (size_t)row * D + d;
                        float cc = sigf(gf) * g_c[hidx] + sigf(gi) * tanhf(gg);
                        float h = sigf(go) * tanhf(cc);
                        g_c[hidx] = cc;
                        g_h[hidx] = h;
                        __nv_bfloat16 hh = __float2bfloat16(h);
                        g_A[(size_t)row * 512 + d] = hh;
                        g_A[(size_t)row * 512 + 256 + d] =
                            __float2bfloat16(h - __bfloat162float(hh));
                    }
                }
            }
        }
    }
}

// ---------------------------------------------------------------------------
extern "C" void kernel_launch(void* const* d_in, const int* in_sizes, int n_in,
                              void* d_out, int out_size) {
    const float* x    = (const float*)d_in[0];
    const float* W_ih = (const float*)d_in[1];
    const float* W_hh = (const float*)d_in[2];
    const float* b_ih = (const float*)d_in[3];
    const float* b_hh = (const float*)d_in[4];
    const void*  idx  = d_in[5];
    int N = in_sizes[5];
    int G = out_size / (2 * D);      // 4096
    float* out = (float*)d_out;

    static cudaStream_t side = nullptr;
    static cudaEvent_t evF[2], evH[2];
    if (!side) {
        cudaStreamCreateWithFlags(&side, cudaStreamNonBlocking);
        for (int i = 0; i < 2; i++) {
            cudaEventCreateWithFlags(&evF[i], cudaEventDisableTiming);
            cudaEventCreateWithFlags(&evH[i], cudaEventDisableTiming);
        }
    }
    static const int SMEM_GEMM = 2 * SSTG * (int)sizeof(__nv_bfloat16);  // 128KB
    cudaFuncSetAttribute(gemm_half, cudaFuncAttributeMaxDynamicSharedMemorySize,
                         SMEM_GEMM);

    int prep_total = 512 * 512;
    prep_kernel<<<(prep_total + 255) / 256, 256>>>(W_ih, W_hh, b_ih, b_hh, idx, N, G);
    init_state_kernel<<<(G * D + 255) / 256, 256>>>(G);

    dim3 ggrid(G / 128, 512 / 128);
    for (int s = 0; s < 2; s++) {
        // fork: h-contribution GEMM runs concurrent with the segment pass
        cudaEventRecord(evF[s], 0);
        cudaStreamWaitEvent(side, evF[s], 0);
        gemm_half<<<ggrid, 256, SMEM_GEMM, side>>>(0, 0);
        cudaEventRecord(evH[s], side);

        // serpentine: pass 0 forward, pass 1 reverse
        segment_kernel<<<G, 256>>>(x, nullptr, 1, s & 1);

        // join, then r-contribution GEMM with fused LSTM epilogue
        cudaStreamWaitEvent(0, evH[s], 0);
        gemm_half<<<ggrid, 256, SMEM_GEMM>>>(1, 1);
    }
    // pass 2 forward again (tail of reverse pass = head of x is L2-hot)
    segment_kernel<<<G, 256>>>(x, out, 0, 0);
}

// round 16
// speedup vs baseline: 1.1819x; 1.1819x over previous
#include <cuda_runtime.h>
#include <cuda_bf16.h>
#include <math.h>

#define D 128
#define GMAX 4096
#define NMAX 500000

__device__ float g_h[GMAX * D];
__device__ float g_c[GMAX * D];
__device__ float g_r[GMAX * D];
__device__ float g_gates[GMAX * 4 * D];
__device__ float g_bias[4 * D];
__device__ int   g_segstart[GMAX + 1];

// bf16 split operands for tensor-core GEMM (16B-aligned for cp.async):
__device__ __align__(16) __nv_bfloat16 g_A[GMAX * 512];
__device__ __align__(16) __nv_bfloat16 g_Wb[512 * 512];

__device__ __forceinline__ float sigf(float v) {
    return 1.0f / (1.0f + __expf(-v));
}

__device__ __forceinline__ unsigned smem_u32(const void* p) {
    return (unsigned)__cvta_generic_to_shared(p);
}
__device__ __forceinline__ void cp16(void* dst, const void* src) {
    asm volatile("cp.async.cg.shared.global [%0], [%1], 16;\n"
                 :: "r"(smem_u32(dst)), "l"(src));
}
__device__ __forceinline__ void cp_commit() {
    asm volatile("cp.async.commit_group;\n");
}
template <int N> __device__ __forceinline__ void cp_wait() {
    asm volatile("cp.async.wait_group %0;\n" :: "n"(N));
}
__device__ __forceinline__ void ldsm4(unsigned& r0, unsigned& r1, unsigned& r2,
                                      unsigned& r3, const void* p) {
    asm volatile("ldmatrix.sync.aligned.m8n8.x4.shared.b16 {%0,%1,%2,%3}, [%4];"
                 : "=r"(r0), "=r"(r1), "=r"(r2), "=r"(r3)
                 : "r"(smem_u32(p)));
}
__device__ __forceinline__ void pfL2(const void* p) {
    asm volatile("prefetch.global.L2 [%0];" :: "l"(p));
}

// ---------------------------------------------------------------------------
__global__ void prep_kernel(const float* __restrict__ W_ih,
                            const float* __restrict__ W_hh,
                            const float* __restrict__ b_ih,
                            const float* __restrict__ b_hh,
                            const void* __restrict__ index_raw,
                            int N, int G) {
    int tid = blockIdx.x * blockDim.x + threadIdx.x;

    if (tid < 512 * 512) {
        int n = tid >> 9, k = tid & 511;
        int kk = k & 255;
        float w = W_ih[(size_t)n * 256 + kk];
        if (kk < D) w += W_hh[(size_t)n * D + kk];
        __nv_bfloat16 hi = __float2bfloat16(w);
        if (k < 256) g_Wb[tid] = hi;
        else         g_Wb[tid] = __float2bfloat16(w - __bfloat162float(hi));
    }
    if (tid < 4 * D) g_bias[tid] = b_ih[tid] + b_hh[tid];

    if (tid <= G) {
        const int* p32 = (const int*)index_raw;
        int j1 = N - 1;
        if ((j1 & 1) == 0) j1--;
        int is64 = 1;
        if (j1 >= 5) {
            if (p32[j1] != 0 || p32[j1 - 2] != 0 || p32[j1 - 4] != 0) is64 = 0;
        }
        const long long* p64 = (const long long*)index_raw;
        int lo = 0, hi = N;
        while (lo < hi) {
            int mid = (lo + hi) >> 1;
            long long v = is64 ? p64[mid] : (long long)p32[mid];
            if (v < (long long)tid) lo = mid + 1; else hi = mid;
        }
        g_segstart[tid] = lo;
    }
}

// ---------------------------------------------------------------------------
__global__ void init_state_kernel(int G) {
    int tid = blockIdx.x * blockDim.x + threadIdx.x;
    if (tid >= G * D) return;
    int row = tid / D, d = tid % D;
    float bi = g_bias[d], bg = g_bias[2 * D + d], bo = g_bias[3 * D + d];
    float c = sigf(bi) * tanhf(bg);
    float h = sigf(bo) * tanhf(c);
    g_c[tid] = c;
    g_h[tid] = h;
    __nv_bfloat16 hh = __float2bfloat16(h);
    g_A[(size_t)row * 512 + d] = hh;
    g_A[(size_t)row * 512 + 256 + d] = __float2bfloat16(h - __bfloat162float(hh));
}

// ---------------------------------------------------------------------------
// segment attention (direct LDG) + depth-1 L2 prefetch (R13 proven config).
// 8-lane groups, branchless shared-offset softmax, serpentine via rev.
// ---------------------------------------------------------------------------
__global__ void __launch_bounds__(256) segment_kernel(const float* __restrict__ x,
                                                      float* __restrict__ out,
                                                      int writeA, int rev) {
    int g = rev ? ((int)gridDim.x - 1 - (int)blockIdx.x) : (int)blockIdx.x;
    int start = g_segstart[g];
    int end   = g_segstart[g + 1];

    __shared__ __align__(16) float wacc[32][D];
    __shared__ __align__(16) float qs[D];
    __shared__ float ws[32];
    __shared__ float winv;

    int tid = threadIdx.x, warp = tid >> 5, lane = tid & 31;
    int grp = lane >> 3, sub = lane & 7;
    int gidx = warp * 4 + grp;
    unsigned gmask = 0xFFu << (grp * 8);

    if (tid < D) qs[tid] = g_h[(size_t)g * D + tid];
    __syncthreads();

    const float4* q4 = (const float4*)qs;
    float4 q0 = q4[sub], q1 = q4[sub + 8], q2 = q4[sub + 16], q3 = q4[sub + 24];

    float s = 0.0f;
    float4 a0 = make_float4(0.f, 0.f, 0.f, 0.f);
    float4 a1 = a0, a2 = a0, a3 = a0;

    if (start < end) {
        const float4* fp = (const float4*)(x + (size_t)start * D);
        float4 f0 = fp[sub], f1 = fp[sub + 8], f2 = fp[sub + 16], f3 = fp[sub + 24];
        float m = f0.x * q0.x + f0.y * q0.y + f0.z * q0.z + f0.w * q0.w
                + f1.x * q1.x + f1.y * q1.y + f1.z * q1.z + f1.w * q1.w
                + f2.x * q2.x + f2.y * q2.y + f2.z * q2.z + f2.w * q2.w
                + f3.x * q3.x + f3.y * q3.y + f3.z * q3.z + f3.w * q3.w;
        m += __shfl_xor_sync(gmask, m, 1);
        m += __shfl_xor_sync(gmask, m, 2);
        m += __shfl_xor_sync(gmask, m, 4);

        for (int row = start + gidx; row < end; row += 32) {
            const float4* xp = (const float4*)(x + (size_t)row * D);
            int nrow = row + 32;
            if (nrow < end) {
                const char* np = (const char*)(x + (size_t)nrow * D) + sub * 16;
                pfL2(np); pfL2(np + 128); pfL2(np + 256); pfL2(np + 384);
            }
            float4 v0 = xp[sub], v1 = xp[sub + 8];
            float4 v2 = xp[sub + 16], v3 = xp[sub + 24];
            float d = v0.x * q0.x + v0.y * q0.y + v0.z * q0.z + v0.w * q0.w
                    + v1.x * q1.x + v1.y * q1.y + v1.z * q1.z + v1.w * q1.w
                    + v2.x * q2.x + v2.y * q2.y + v2.z * q2.z + v2.w * q2.w
                    + v3.x * q3.x + v3.y * q3.y + v3.z * q3.z + v3.w * q3.w;
            d += __shfl_xor_sync(gmask, d, 1);
            d += __shfl_xor_sync(gmask, d, 2);
            d += __shfl_xor_sync(gmask, d, 4);
            float p = __expf(d - m);
            s += p;
            a0.x += p * v0.x; a0.y += p * v0.y; a0.z += p * v0.z; a0.w += p * v0.w;
            a1.x += p * v1.x; a1.y += p * v1.y; a1.z += p * v1.z; a1.w += p * v1.w;
            a2.x += p * v2.x; a2.y += p * v2.y; a2.z += p * v2.z; a2.w += p * v2.w;
            a3.x += p * v3.x; a3.y += p * v3.y; a3.z += p * v3.z; a3.w += p * v3.w;
        }
    }

    float4* wp = (float4*)wacc[gidx];
    wp[sub] = a0; wp[sub + 8] = a1; wp[sub + 16] = a2; wp[sub + 24] = a3;
    if (sub == 0) ws[gidx] = s;
    __syncthreads();

    if (tid == 0) {
        float S = 0.0f;
        #pragma unroll
        for (int i = 0; i < 32; i++) S += ws[i];
        winv = 1.0f / fmaxf(S, 1e-16f);
    }
    __syncthreads();

    if (tid < D) {
        float inv = winv;
        float r = 0.0f;
        #pragma unroll
        for (int w = 0; w < 32; w++) r += wacc[w][tid];
        r *= inv;
        if (writeA) {
            g_r[(size_t)g * D + tid] = r;
            __nv_bfloat16 hh = __float2bfloat16(r);
            g_A[(size_t)g * 512 + 128 + tid] = hh;
            g_A[(size_t)g * 512 + 384 + tid] = __float2bfloat16(r - __bfloat162float(hh));
        }
        if (out) {
            out[(size_t)g * 256 + tid] = qs[tid];
            out[(size_t)g * 256 + 128 + tid] = r;
        }
    }
}

// ---------------------------------------------------------------------------
#define TS 8192
#define SSTG (4 * TS)

__device__ __forceinline__ __nv_bfloat16* swaddr(__nv_bfloat16* base, int row, int k) {
    int kb = k >> 3, ko = k & 7;
    return base + row * 64 + ((kb ^ (row & 7)) << 3) + ko;
}

__global__ void __launch_bounds__(256, 1) gemm_half(int part, int accum) {
    extern __shared__ __align__(16) __nv_bfloat16 sm[];

    int bm = blockIdx.x * 128;
    int bn = blockIdx.y * 128;
    int t = threadIdx.x, warp = t >> 5, lane = t & 31;
    int wm_ = (warp & 3) * 32;
    int wn_ = (warp >> 2) * 64;
    int gid = lane >> 2, tig = lane & 3;

    int a_row_off = (lane & 7) + (lane & 8);
    int a_k_off   = (lane >> 4) << 3;
    int b_row_off = (lane & 7) + ((lane >> 4) << 3);
    int b_k_off   = ((lane >> 3) & 1) << 3;

    float acc[2][8][4];
    #pragma unroll
    for (int mi = 0; mi < 2; mi++)
        #pragma unroll
        for (int ni = 0; ni < 8; ni++)
            #pragma unroll
            for (int cc = 0; cc < 4; cc++) acc[mi][ni][cc] = 0.0f;

    auto issue_load = [&](int stage, int c) {
        int kb = part * 128 + c * 64;
        __nv_bfloat16* st = sm + stage * SSTG;
        #pragma unroll
        for (int i = 0; i < 4; i++) {
            int idx = t + i * 256;
            int row = idx >> 3, c8 = idx & 7;
            unsigned sw = row * 64 + ((c8 ^ (row & 7)) << 3);
            const __nv_bfloat16* arow = g_A + (size_t)(bm + row) * 512;
            cp16(st + sw,            arow + kb + c8 * 8);
            cp16(st + TS + sw,       arow + 256 + kb + c8 * 8);
            const __nv_bfloat16* brow = g_Wb + (size_t)(bn + row) * 512;
            cp16(st + 2 * TS + sw,   brow + kb + c8 * 8);
            cp16(st + 3 * TS + sw,   brow + 256 + kb + c8 * 8);
        }
        cp_commit();
    };

    issue_load(0, 0);

    for (int c = 0; c < 2; c++) {
        if (c == 0) {
            issue_load(1, 1);
            cp_wait<1>();
        } else {
            cp_wait<0>();
        }
        __syncthreads();

        __nv_bfloat16* Ahi = sm + c * SSTG;
        __nv_bfloat16* Alo = Ahi + TS;
        __nv_bfloat16* Bhi = Ahi + 2 * TS;
        __nv_bfloat16* Blo = Ahi + 3 * TS;

        #pragma unroll
        for (int k0 = 0; k0 < 64; k0 += 16) {
            unsigned ah[2][4], al[2][4];
            #pragma unroll
            for (int mi = 0; mi < 2; mi++) {
                ldsm4(ah[mi][0], ah[mi][1], ah[mi][2], ah[mi][3],
                      swaddr(Ahi, wm_ + mi * 16 + a_row_off, k0 + a_k_off));
                ldsm4(al[mi][0], al[mi][1], al[mi][2], al[mi][3],
                      swaddr(Alo, wm_ + mi * 16 + a_row_off, k0 + a_k_off));
            }
            unsigned bh[4][4], bl[4][4];
            #pragma unroll
            for (int np = 0; np < 4; np++) {
                ldsm4(bh[np][0], bh[np][1], bh[np][2], bh[np][3],
                      swaddr(Bhi, wn_ + np * 16 + b_row_off, k0 + b_k_off));
                ldsm4(bl[np][0], bl[np][1], bl[np][2], bl[np][3],
                      swaddr(Blo, wn_ + np * 16 + b_row_off, k0 + b_k_off));
            }
            #pragma unroll
            for (int mi = 0; mi < 2; mi++) {
                #pragma unroll
                for (int ni = 0; ni < 8; ni++) {
                    int np = ni >> 1, hf = ni & 1;
                    asm volatile(
                        "mma.sync.aligned.m16n8k16.row.col.f32.bf16.bf16.f32 "
                        "{%0,%1,%2,%3}, {%4,%5,%6,%7}, {%8,%9}, {%0,%1,%2,%3};\n"
                        : "+f"(acc[mi][ni][0]), "+f"(acc[mi][ni][1]),
                          "+f"(acc[mi][ni][2]), "+f"(acc[mi][ni][3])
                        : "r"(ah[mi][0]), "r"(ah[mi][1]), "r"(ah[mi][2]), "r"(ah[mi][3]),
                          "r"(bh[np][hf * 2]), "r"(bh[np][hf * 2 + 1]));
                    asm volatile(
                        "mma.sync.aligned.m16n8k16.row.col.f32.bf16.bf16.f32 "
                        "{%0,%1,%2,%3}, {%4,%5,%6,%7}, {%8,%9}, {%0,%1,%2,%3};\n"
                        : "+f"(acc[mi][ni][0]), "+f"(acc[mi][ni][1]),
                          "+f"(acc[mi][ni][2]), "+f"(acc[mi][ni][3])
                        : "r"(ah[mi][0]), "r"(ah[mi][1]), "r"(ah[mi][2]), "r"(ah[mi][3]),
                          "r"(bl[np][hf * 2]), "r"(bl[np][hf * 2 + 1]));
                    asm volatile(
                        "mma.sync.aligned.m16n8k16.row.col.f32.bf16.bf16.f32 "
                        "{%0,%1,%2,%3}, {%4,%5,%6,%7}, {%8,%9}, {%0,%1,%2,%3};\n"
                        : "+f"(acc[mi][ni][0]), "+f"(acc[mi][ni][1]),
                          "+f"(acc[mi][ni][2]), "+f"(acc[mi][ni][3])
                        : "r"(al[mi][0]), "r"(al[mi][1]), "r"(al[mi][2]), "r"(al[mi][3]),
                          "r"(bh[np][hf * 2]), "r"(bh[np][hf * 2 + 1]));
                }
            }
        }
        __syncthreads();
    }

    #pragma unroll
    for (int mi = 0; mi < 2; mi++) {
        #pragma unroll
        for (int rr = 0; rr < 2; rr++) {
            int row = bm + wm_ + mi * 16 + rr * 8 + gid;
            #pragma unroll
            for (int ni = 0; ni < 8; ni++) {
                int col = bn + wn_ + ni * 8 + tig * 2;
                float2 v = make_float2(acc[mi][ni][rr * 2], acc[mi][ni][rr * 2 + 1]);
                float2* p = (float2*)(g_gates + (size_t)row * 512 + col);
                if (accum) { float2 o = *p; v.x += o.x; v.y += o.y; }
                *p = v;
            }
        }
    }
}

// ---------------------------------------------------------------------------
__global__ void lstm_update(int G) {
    int tid = blockIdx.x * blockDim.x + threadIdx.x;
    if (tid >= G * D) return;
    int row = tid / D, d = tid % D;
    const float* gr = g_gates + (size_t)row * 4 * D;
    float gi = gr[d]         + g_bias[d];
    float gf = gr[D + d]     + g_bias[D + d];
    float gg = gr[2 * D + d] + g_bias[2 * D + d];
    float go = gr[3 * D + d] + g_bias[3 * D + d];
    float c = sigf(gf) * g_c[tid] + sigf(gi) * tanhf(gg);
    float h = sigf(go) * tanhf(c);
    g_c[tid] = c;
    g_h[tid] = h;
    __nv_bfloat16 hh = __float2bfloat16(h);
    g_A[(size_t)row * 512 + d] = hh;
    g_A[(size_t)row * 512 + 256 + d] = __float2bfloat16(h - __bfloat162float(hh));
}

// ---------------------------------------------------------------------------
extern "C" void kernel_launch(void* const* d_in, const int* in_sizes, int n_in,
                              void* d_out, int out_size) {
    const float* x    = (const float*)d_in[0];
    const float* W_ih = (const float*)d_in[1];
    const float* W_hh = (const float*)d_in[2];
    const float* b_ih = (const float*)d_in[3];
    const float* b_hh = (const float*)d_in[4];
    const void*  idx  = d_in[5];
    int N = in_sizes[5];
    int G = out_size / (2 * D);      // 4096
    float* out = (float*)d_out;

    static cudaStream_t side = nullptr;
    static cudaEvent_t evF[2], evH[2];
    if (!side) {
        cudaStreamCreateWithFlags(&side, cudaStreamNonBlocking);
        for (int i = 0; i < 2; i++) {
            cudaEventCreateWithFlags(&evF[i], cudaEventDisableTiming);
            cudaEventCreateWithFlags(&evH[i], cudaEventDisableTiming);
        }
    }
    static const int SMEM_GEMM = 2 * SSTG * (int)sizeof(__nv_bfloat16);  // 128KB
    cudaFuncSetAttribute(gemm_half, cudaFuncAttributeMaxDynamicSharedMemorySize,
                         SMEM_GEMM);

    int prep_total = 512 * 512;
    prep_kernel<<<(prep_total + 255) / 256, 256>>>(W_ih, W_hh, b_ih, b_hh, idx, N, G);
    init_state_kernel<<<(G * D + 255) / 256, 256>>>(G);

    dim3 ggrid(G / 128, 512 / 128);
    for (int s = 0; s < 2; s++) {
        // fork: h-contribution GEMM runs concurrent with the segment pass
        cudaEventRecord(evF[s], 0);
        cudaStreamWaitEvent(side, evF[s], 0);
        gemm_half<<<ggrid, 256, SMEM_GEMM, side>>>(0, 0);
        cudaEventRecord(evH[s], side);

        // serpentine: pass 0 forward, pass 1 reverse
        segment_kernel<<<G, 256>>>(x, nullptr, 1, s & 1);

        cudaStreamWaitEvent(0, evH[s], 0);
        gemm_half<<<ggrid, 256, SMEM_GEMM>>>(1, 1);
        lstm_update<<<(G * D + 255) / 256, 256>>>(G);
    }
    // pass 2 forward again (tail of reverse pass = head of x is L2-hot)
    segment_kernel<<<G, 256>>>(x, out, 0, 0);
}